// round 14
// baseline (speedup 1.0000x reference)
#include <cuda_runtime.h>
#include <cuda_fp16.h>
#include <math.h>
#include <stdint.h>

// ============================================================================
// Problem constants
// ============================================================================
#define B_   4
#define S_   2048
#define IN_  512
#define H_   1024
#define M_   (B_ * S_)   // 8192
#define AW   33          // 2*atten_size + 1

// ============================================================================
// Device global scratch (allocation-free per harness rules)
// ============================================================================
__device__ __half g_xhi[(size_t)M_ * IN_];
__device__ __half g_hhi[(size_t)M_ * H_];
__device__ __half g_qhi[(size_t)M_ * H_];
__device__ __half g_w1t_hi[(size_t)H_ * IN_];   // W1^T [1024,512]
__device__ __half g_wqt_hi[(size_t)H_ * H_];    // Wq^T [1024,1024]

// ============================================================================
// PTX helpers (base sm_103 ISA only: cp.async, ldmatrix, mma.sync)
// ============================================================================
__device__ __forceinline__ uint32_t smem_u32(const void* p) {
    uint32_t a;
    asm("{ .reg .u64 t; cvta.to.shared.u64 t, %1; cvt.u32.u64 %0, t; }"
        : "=r"(a) : "l"(p));
    return a;
}

__device__ __forceinline__ void cp_async16(uint32_t dst, const void* src) {
    asm volatile("cp.async.cg.shared.global [%0], [%1], 16;"
                 :: "r"(dst), "l"(src));
}
#define CP_COMMIT() asm volatile("cp.async.commit_group;" ::: "memory")
#define CP_WAIT(n)  asm volatile("cp.async.wait_group %0;" :: "n"(n) : "memory")

__device__ __forceinline__ void ldsm_x4(uint32_t* r, uint32_t addr) {
    asm volatile("ldmatrix.sync.aligned.m8n8.x4.shared.b16 {%0,%1,%2,%3}, [%4];"
                 : "=r"(r[0]), "=r"(r[1]), "=r"(r[2]), "=r"(r[3]) : "r"(addr));
}

__device__ __forceinline__ void mma_f16(float* c, const uint32_t* a,
                                        uint32_t b0, uint32_t b1) {
    asm volatile(
        "mma.sync.aligned.m16n8k16.row.col.f32.f16.f16.f32 "
        "{%0,%1,%2,%3}, {%4,%5,%6,%7}, {%8,%9}, {%0,%1,%2,%3};"
        : "+f"(c[0]), "+f"(c[1]), "+f"(c[2]), "+f"(c[3])
        : "r"(a[0]), "r"(a[1]), "r"(a[2]), "r"(a[3]), "r"(b0), "r"(b1));
}

// unpack 8 halves (uint4) -> 8 floats
__device__ __forceinline__ void h8_to_f8(uint4 v, float* f) {
    union { uint32_t u; __half2 h; } c;
    c.u = v.x; float2 t0 = __half22float2(c.h);
    c.u = v.y; float2 t1 = __half22float2(c.h);
    c.u = v.z; float2 t2 = __half22float2(c.h);
    c.u = v.w; float2 t3 = __half22float2(c.h);
    f[0] = t0.x; f[1] = t0.y; f[2] = t1.x; f[3] = t1.y;
    f[4] = t2.x; f[5] = t2.y; f[6] = t3.x; f[7] = t3.y;
}

// ============================================================================
// Convert kernels
// ============================================================================
__global__ void split_hi_kernel(const float* __restrict__ in,
                                __half* __restrict__ hi, int n4) {
    int i = blockIdx.x * blockDim.x + threadIdx.x;
    if (i >= n4) return;
    float4 v = ((const float4*)in)[i];
    ((__half2*)hi)[i * 2 + 0] = __halves2half2(__float2half_rn(v.x),
                                               __float2half_rn(v.y));
    ((__half2*)hi)[i * 2 + 1] = __halves2half2(__float2half_rn(v.z),
                                               __float2half_rn(v.w));
}

// Merged transpose for both weights: by<16 -> W1 [512,1024], else Wq [1024,1024]
__global__ void transpose_both_kernel(const float* __restrict__ W1,
                                      __half* __restrict__ w1T,
                                      const float* __restrict__ Wq,
                                      __half* __restrict__ wqT) {
    __shared__ float t[32][33];
    const bool isW1 = (blockIdx.y < 16);
    const float* in = isW1 ? W1 : Wq;
    __half* outT = isW1 ? w1T : wqT;
    const int R = isW1 ? IN_ : H_;
    const int C = H_;
    const int c0 = blockIdx.x * 32;
    const int r0 = (isW1 ? blockIdx.y : (blockIdx.y - 16)) * 32;
    const int tx = threadIdx.x, ty = threadIdx.y;   // 32 x 8
    #pragma unroll
    for (int j = 0; j < 32; j += 8)
        t[ty + j][tx] = in[(size_t)(r0 + ty + j) * C + c0 + tx];
    __syncthreads();
    #pragma unroll
    for (int j = 0; j < 32; j += 8)
        outT[(size_t)(c0 + ty + j) * R + r0 + tx] = __float2half_rn(t[tx][ty + j]);
}

// ============================================================================
// HMMA GEMM (fp32 accum, 1-term fp16) — round-10 proven config.
// C[M,N] = A[M,K] @ W[K,N], W transposed [N,K].
// Block tile 256x128, BK=64/stage, 16 warps (warp tile 64x32), NST=4.
// ============================================================================
#define NST 4
#define A_BYTES 32768                    // 256 rows x 128B
#define STAGE_BYTES (A_BYTES + 16384)    // + B: 128 rows x 128B
#define GEMM_SMEM (NST * STAGE_BYTES)    // 192 KB

template <bool RELU_BIAS>
__global__ __launch_bounds__(512, 1)
void hmma_gemm(const __half* __restrict__ Ahi,
               const __half* __restrict__ Bhi,
               const float* __restrict__ bias,
               __half* __restrict__ outHi,
               int K)
{
    extern __shared__ __align__(1024) char smem[];
    const uint32_t smBase = smem_u32(smem);

    const int tid  = threadIdx.x;
    const int wid  = tid >> 5;
    const int lane = tid & 31;
    const int m0 = blockIdx.y * 256;
    const int n0 = blockIdx.x * 128;
    const int nk = K / 64;

    const int wm = (wid & 3) * 64;
    const int wn = (wid >> 2) * 32;

    const int half_sel = tid & 1;
    const int arow = tid >> 1;
    const bool loadB = (tid < 256);
    const int brow = (tid >> 1) & 127;
    const __half* srcA = Ahi + (size_t)(m0 + arow) * K + half_sel * 32;
    const __half* srcB = Bhi + (size_t)(n0 + brow) * K + half_sel * 32;
    uint32_t dstA[4], dstB[4];
    #pragma unroll
    for (int g = 0; g < 4; g++) {
        const int lg = half_sel * 4 + g;
        dstA[g] = smBase + arow * 128 + ((lg ^ (arow & 7)) * 16);
        dstB[g] = smBase + A_BYTES + brow * 128 + ((lg ^ (brow & 7)) * 16);
    }

    auto load_stage = [&](int c, int s) {
        const uint32_t so = s * STAGE_BYTES;
        const __half* sa = srcA + c * 64;
        #pragma unroll
        for (int g = 0; g < 4; g++)
            cp_async16(dstA[g] + so, sa + g * 8);
        if (loadB) {
            const __half* sb = srcB + c * 64;
            #pragma unroll
            for (int g = 0; g < 4; g++)
                cp_async16(dstB[g] + so, sb + g * 8);
        }
    };

    float acc[4][4][4];
    #pragma unroll
    for (int mt = 0; mt < 4; mt++)
        #pragma unroll
        for (int nt = 0; nt < 4; nt++)
            #pragma unroll
            for (int j = 0; j < 4; j++)
                acc[mt][nt][j] = 0.f;

    #pragma unroll
    for (int c = 0; c < NST - 1; c++) {
        load_stage(c, c);
        CP_COMMIT();
    }

    const int arow_l = (lane & 15);
    const int agrp_l = (lane >> 4);
    const int brow_l = (lane & 7) + ((lane >> 4) << 3);
    const int bgrp_l = (lane >> 3) & 1;

    for (int c = 0; c < nk; c++) {
        CP_WAIT(NST - 2);
        __syncthreads();
        if (c + NST - 1 < nk)
            load_stage(c + NST - 1, (c + NST - 1) % NST);
        CP_COMMIT();

        const uint32_t aB = smBase + (c % NST) * STAGE_BYTES;
        const uint32_t bB = aB + A_BYTES;

        #pragma unroll
        for (int ks = 0; ks < 4; ks++) {
            const int agH = ks * 2 + agrp_l;
            const int bgH = ks * 2 + bgrp_l;

            uint32_t bf[2][4];
            #pragma unroll
            for (int np = 0; np < 2; np++) {
                const int r = wn + np * 16 + brow_l;
                ldsm_x4(bf[np], bB + r * 128 + ((bgH ^ (r & 7)) * 16));
            }

            #pragma unroll
            for (int mt = 0; mt < 4; mt++) {
                const int r = wm + mt * 16 + arow_l;
                uint32_t af[4];
                ldsm_x4(af, aB + r * 128 + ((agH ^ (r & 7)) * 16));
                #pragma unroll
                for (int nt = 0; nt < 4; nt++) {
                    const int np = nt >> 1, o = (nt & 1) * 2;
                    mma_f16(acc[mt][nt], af, bf[np][o], bf[np][o + 1]);
                }
            }
        }
    }

    const int r0 = lane >> 2;
    const int c0 = (lane & 3) * 2;

    #pragma unroll
    for (int mt = 0; mt < 4; mt++) {
        #pragma unroll
        for (int h = 0; h < 2; h++) {
            const int row_o = m0 + wm + mt * 16 + h * 8 + r0;
            __half* op = outHi + (size_t)row_o * H_ + n0 + wn + c0;
            #pragma unroll
            for (int nt = 0; nt < 4; nt++) {
                float vx = acc[mt][nt][h * 2 + 0];
                float vy = acc[mt][nt][h * 2 + 1];
                if (RELU_BIAS) {
                    const int gc = n0 + wn + nt * 8 + c0;
                    vx = fmaxf(vx + bias[gc], 0.f);
                    vy = fmaxf(vy + bias[gc + 1], 0.f);
                }
                *(__half2*)(op + nt * 8) =
                    __halves2half2(__float2half_rn(vx), __float2half_rn(vy));
            }
        }
    }
}

// ============================================================================
// Local windowed attention — fp32 smem chunks (instruction-lean inner loops).
// Block: (batch, 16 s).  hs: 48 rows x 512 fp32 cols per chunk (~102KB with
// scores) -> 2 CTAs/SM.  h converted fp16->fp32 ONCE per chunk load; inner
// loops are pure LDS.128 + FFMA.
// ============================================================================
#define TS 16
#define HCH 512            // fp32 cols per chunk
#define HPF 520            // row pitch in floats
#define ATT_SMEM (48 * HPF * 4 + TS * 36 * 4)

__global__ __launch_bounds__(256, 2)
void atten_kernel(const __half* __restrict__ hh, const __half* __restrict__ qh,
                  float* __restrict__ out)
{
    extern __shared__ __align__(16) char asmem[];
    float* hs = (float*)asmem;                         // [48][HPF]
    float (*sc)[36] = (float(*)[36])(asmem + 48 * HPF * 4);

    const int tid = threadIdx.x;
    const int b = blockIdx.y;
    const int s0 = blockIdx.x * TS;

    const __half* hB = hh + (size_t)b * S_ * H_;
    const __half* qB = qh + (size_t)b * S_ * H_;
    float*        oB = out + (size_t)b * S_ * H_;

    auto load_chunk = [&](int kc) {
        for (int i = tid; i < 48 * (HCH / 8); i += 256) {   // 48 x 64 uint4
            const int r = i >> 6;
            const int c8 = (i & 63) * 8;
            const int g = s0 - 16 + r;
            uint4 v = make_uint4(0, 0, 0, 0);
            if (g >= 0 && g < S_)
                v = *(const uint4*)(hB + (size_t)g * H_ + kc + c8);
            float f[8];
            h8_to_f8(v, f);
            float* dst = &hs[r * HPF + c8];
            *(float4*)dst       = make_float4(f[0], f[1], f[2], f[3]);
            *(float4*)(dst + 4) = make_float4(f[4], f[5], f[6], f[7]);
        }
    };

    // ---------------- Phase A: scores ----------------
    const int warp = tid >> 5, lane = tid & 31;
    const int lane16 = lane & 15;
    const int sA = warp * 2 + (lane >> 4);   // 0..15
    const int kofs = lane16 * 8;             // 0..120

    float acc[AW];
    #pragma unroll
    for (int w = 0; w < AW; w++) acc[w] = 0.f;

    for (int chunk = 0; chunk < 2; chunk++) {
        __syncthreads();
        load_chunk(chunk * HCH);
        __syncthreads();

        #pragma unroll
        for (int pass = 0; pass < 4; pass++) {
            const int kl = pass * 128 + kofs;
            float qv[8];
            h8_to_f8(*(const uint4*)(qB + (size_t)(s0 + sA) * H_
                                     + chunk * HCH + kl), qv);
            #pragma unroll
            for (int w = 0; w < AW; w++) {
                const float* hr = &hs[(sA + 32 - w) * HPF + kl];
                const float4 ha = *(const float4*)hr;
                const float4 hb = *(const float4*)(hr + 4);
                acc[w] += qv[0] * ha.x + qv[1] * ha.y + qv[2] * ha.z
                        + qv[3] * ha.w + qv[4] * hb.x + qv[5] * hb.y
                        + qv[6] * hb.z + qv[7] * hb.w;
            }
        }
    }

    #pragma unroll
    for (int w = 0; w < AW; w++) {
        #pragma unroll
        for (int d = 8; d >= 1; d >>= 1)
            acc[w] += __shfl_xor_sync(0xffffffffu, acc[w], d);
    }
    #pragma unroll
    for (int w = 0; w < AW; w++) {
        if ((w & 15) == lane16 && (w < 32 || lane16 == 0))
            sc[sA][w] = acc[w] * 0.03125f;   // 1/sqrt(1024)
    }
    __syncthreads();

    // ---------------- Phase B: softmax ----------------
    if (tid < TS) {
        float m = -1e30f;
        for (int w = 0; w < AW; w++) m = fmaxf(m, sc[tid][w]);
        float sum = 0.f;
        for (int w = 0; w < AW; w++) {
            const float e = expf(sc[tid][w] - m);
            sc[tid][w] = e;
            sum += e;
        }
        const float inv = 1.f / sum;
        for (int w = 0; w < AW; w++) sc[tid][w] *= inv;
    }

    // ---------------- Phase C: weighted sum ----------------
    const int sg = ((tid >> 4) & 7) * 2;     // s pair
    const int cg = (tid & 15) * 8;           // 0..120
    const int hsel = tid >> 7;               // 0/1

    for (int chunk = 0; chunk < 2; chunk++) {
        __syncthreads();                     // covers softmax + prior readers
        load_chunk(chunk * HCH);
        __syncthreads();

        #pragma unroll
        for (int ci = 0; ci < 2; ci++) {
            const int kl = hsel * 256 + ci * 128 + cg;
            float a0[8], a1[8];
            #pragma unroll
            for (int k = 0; k < 8; k++) { a0[k] = 0.f; a1[k] = 0.f; }

            #pragma unroll
            for (int j = 0; j < 34; j++) {
                const float* hr = &hs[(sg + j) * HPF + kl];
                const float4 ha = *(const float4*)hr;
                const float4 hb = *(const float4*)(hr + 4);
                if (j <= 32) {
                    const float p = sc[sg][32 - j];
                    a0[0] += p * ha.x; a0[1] += p * ha.y;
                    a0[2] += p * ha.z; a0[3] += p * ha.w;
                    a0[4] += p * hb.x; a0[5] += p * hb.y;
                    a0[6] += p * hb.z; a0[7] += p * hb.w;
                }
                if (j >= 1) {
                    const float p = sc[sg + 1][33 - j];
                    a1[0] += p * ha.x; a1[1] += p * ha.y;
                    a1[2] += p * ha.z; a1[3] += p * ha.w;
                    a1[4] += p * hb.x; a1[5] += p * hb.y;
                    a1[6] += p * hb.z; a1[7] += p * hb.w;
                }
            }
            float* o0 = oB + (size_t)(s0 + sg) * H_ + chunk * HCH + kl;
            float* o1 = oB + (size_t)(s0 + sg + 1) * H_ + chunk * HCH + kl;
            *(float4*)(o0)     = make_float4(a0[0], a0[1], a0[2], a0[3]);
            *(float4*)(o0 + 4) = make_float4(a0[4], a0[5], a0[6], a0[7]);
            *(float4*)(o1)     = make_float4(a1[0], a1[1], a1[2], a1[3]);
            *(float4*)(o1 + 4) = make_float4(a1[4], a1[5], a1[6], a1[7]);
        }
    }
}

// ============================================================================
// Launch
// ============================================================================
extern "C" void kernel_launch(void* const* d_in, const int* in_sizes, int n_in,
                              void* d_out, int out_size)
{
    const float* x  = (const float*)d_in[0];   // [4,2048,512]
    const float* W1 = (const float*)d_in[1];   // [512,1024]
    const float* b1 = (const float*)d_in[2];   // [1024]
    const float* Wq = (const float*)d_in[3];   // [1024,1024]
    float* out = (float*)d_out;                // [4,2048,1024]

    __half *xhi, *hhi, *qhi, *w1thi, *wqthi;
    cudaGetSymbolAddress((void**)&xhi, g_xhi);
    cudaGetSymbolAddress((void**)&hhi, g_hhi);
    cudaGetSymbolAddress((void**)&qhi, g_qhi);
    cudaGetSymbolAddress((void**)&w1thi, g_w1t_hi);
    cudaGetSymbolAddress((void**)&wqthi, g_wqt_hi);

    cudaFuncSetAttribute((const void*)hmma_gemm<true>,
                         cudaFuncAttributeMaxDynamicSharedMemorySize, GEMM_SMEM);
    cudaFuncSetAttribute((const void*)hmma_gemm<false>,
                         cudaFuncAttributeMaxDynamicSharedMemorySize, GEMM_SMEM);
    cudaFuncSetAttribute((const void*)atten_kernel,
                         cudaFuncAttributeMaxDynamicSharedMemorySize, ATT_SMEM);

    // Converts
    {
        int n4 = M_ * IN_ / 4;
        split_hi_kernel<<<(n4 + 255) / 256, 256>>>(x, xhi, n4);
        dim3 t(32, 8);
        transpose_both_kernel<<<dim3(32, 48), t>>>(W1, w1thi, Wq, wqthi);
    }

    // GEMM1: hhi = fp16(relu(xhi @ W1hi + b1))
    {
        dim3 grid(H_ / 128, M_ / 256);
        hmma_gemm<true><<<grid, 512, GEMM_SMEM>>>(xhi, w1thi, b1, hhi, IN_);
    }
    // GEMM2: qhi = fp16(hhi @ Wqhi)
    {
        dim3 grid(H_ / 128, M_ / 256);
        hmma_gemm<false><<<grid, 512, GEMM_SMEM>>>(hhi, wqthi, nullptr, qhi, H_);
    }
    // Attention
    {
        dim3 grid(S_ / TS, B_);
        atten_kernel<<<grid, 256, ATT_SMEM>>>(hhi, qhi, out);
    }
}

// round 15
// speedup vs baseline: 1.6625x; 1.6625x over previous
#include <cuda_runtime.h>
#include <cuda_fp16.h>
#include <math.h>
#include <stdint.h>

// ============================================================================
// Problem constants
// ============================================================================
#define B_   4
#define S_   2048
#define IN_  512
#define H_   1024
#define M_   (B_ * S_)   // 8192
#define AW   33          // 2*atten_size + 1

// ============================================================================
// Device global scratch (allocation-free per harness rules)
// ============================================================================
__device__ __half g_xhi[(size_t)M_ * IN_];
__device__ __half g_hhi[(size_t)M_ * H_];
__device__ __half g_qhi[(size_t)M_ * H_];
__device__ __half g_w1t_hi[(size_t)H_ * IN_];   // W1^T [1024,512]
__device__ __half g_wqt_hi[(size_t)H_ * H_];    // Wq^T [1024,1024]

// ============================================================================
// PTX helpers (base sm_103 ISA only: cp.async, ldmatrix, mma.sync)
// ============================================================================
__device__ __forceinline__ uint32_t smem_u32(const void* p) {
    uint32_t a;
    asm("{ .reg .u64 t; cvta.to.shared.u64 t, %1; cvt.u32.u64 %0, t; }"
        : "=r"(a) : "l"(p));
    return a;
}

__device__ __forceinline__ void cp_async16(uint32_t dst, const void* src) {
    asm volatile("cp.async.cg.shared.global [%0], [%1], 16;"
                 :: "r"(dst), "l"(src));
}
#define CP_COMMIT() asm volatile("cp.async.commit_group;" ::: "memory")
#define CP_WAIT(n)  asm volatile("cp.async.wait_group %0;" :: "n"(n) : "memory")

__device__ __forceinline__ void ldsm_x4(uint32_t* r, uint32_t addr) {
    asm volatile("ldmatrix.sync.aligned.m8n8.x4.shared.b16 {%0,%1,%2,%3}, [%4];"
                 : "=r"(r[0]), "=r"(r[1]), "=r"(r[2]), "=r"(r[3]) : "r"(addr));
}
__device__ __forceinline__ void ldsm_x4_t(uint32_t* r, uint32_t addr) {
    asm volatile("ldmatrix.sync.aligned.m8n8.x4.trans.shared.b16 {%0,%1,%2,%3}, [%4];"
                 : "=r"(r[0]), "=r"(r[1]), "=r"(r[2]), "=r"(r[3]) : "r"(addr));
}

__device__ __forceinline__ void mma_f16(float* c, const uint32_t* a,
                                        uint32_t b0, uint32_t b1) {
    asm volatile(
        "mma.sync.aligned.m16n8k16.row.col.f32.f16.f16.f32 "
        "{%0,%1,%2,%3}, {%4,%5,%6,%7}, {%8,%9}, {%0,%1,%2,%3};"
        : "+f"(c[0]), "+f"(c[1]), "+f"(c[2]), "+f"(c[3])
        : "r"(a[0]), "r"(a[1]), "r"(a[2]), "r"(a[3]), "r"(b0), "r"(b1));
}

// ============================================================================
// Convert kernels
// ============================================================================
__global__ void split_hi_kernel(const float* __restrict__ in,
                                __half* __restrict__ hi, int n4) {
    int i = blockIdx.x * blockDim.x + threadIdx.x;
    if (i >= n4) return;
    float4 v = ((const float4*)in)[i];
    ((__half2*)hi)[i * 2 + 0] = __halves2half2(__float2half_rn(v.x),
                                               __float2half_rn(v.y));
    ((__half2*)hi)[i * 2 + 1] = __halves2half2(__float2half_rn(v.z),
                                               __float2half_rn(v.w));
}

// Merged transpose for both weights: by<16 -> W1 [512,1024], else Wq [1024,1024]
__global__ void transpose_both_kernel(const float* __restrict__ W1,
                                      __half* __restrict__ w1T,
                                      const float* __restrict__ Wq,
                                      __half* __restrict__ wqT) {
    __shared__ float t[32][33];
    const bool isW1 = (blockIdx.y < 16);
    const float* in = isW1 ? W1 : Wq;
    __half* outT = isW1 ? w1T : wqT;
    const int R = isW1 ? IN_ : H_;
    const int C = H_;
    const int c0 = blockIdx.x * 32;
    const int r0 = (isW1 ? blockIdx.y : (blockIdx.y - 16)) * 32;
    const int tx = threadIdx.x, ty = threadIdx.y;   // 32 x 8
    #pragma unroll
    for (int j = 0; j < 32; j += 8)
        t[ty + j][tx] = in[(size_t)(r0 + ty + j) * C + c0 + tx];
    __syncthreads();
    #pragma unroll
    for (int j = 0; j < 32; j += 8)
        outT[(size_t)(c0 + ty + j) * R + r0 + tx] = __float2half_rn(t[tx][ty + j]);
}

// ============================================================================
// HMMA GEMM (fp32 accum, fp16) — round-10 proven config.
// Block tile 256x128, BK=64/stage, 16 warps (warp tile 64x32), NST=4.
// ============================================================================
#define NST 4
#define A_BYTES 32768
#define STAGE_BYTES (A_BYTES + 16384)
#define GEMM_SMEM (NST * STAGE_BYTES)    // 192 KB

template <bool RELU_BIAS>
__global__ __launch_bounds__(512, 1)
void hmma_gemm(const __half* __restrict__ Ahi,
               const __half* __restrict__ Bhi,
               const float* __restrict__ bias,
               __half* __restrict__ outHi,
               int K)
{
    extern __shared__ __align__(1024) char smem[];
    const uint32_t smBase = smem_u32(smem);

    const int tid  = threadIdx.x;
    const int wid  = tid >> 5;
    const int lane = tid & 31;
    const int m0 = blockIdx.y * 256;
    const int n0 = blockIdx.x * 128;
    const int nk = K / 64;

    const int wm = (wid & 3) * 64;
    const int wn = (wid >> 2) * 32;

    const int half_sel = tid & 1;
    const int arow = tid >> 1;
    const bool loadB = (tid < 256);
    const int brow = (tid >> 1) & 127;
    const __half* srcA = Ahi + (size_t)(m0 + arow) * K + half_sel * 32;
    const __half* srcB = Bhi + (size_t)(n0 + brow) * K + half_sel * 32;
    uint32_t dstA[4], dstB[4];
    #pragma unroll
    for (int g = 0; g < 4; g++) {
        const int lg = half_sel * 4 + g;
        dstA[g] = smBase + arow * 128 + ((lg ^ (arow & 7)) * 16);
        dstB[g] = smBase + A_BYTES + brow * 128 + ((lg ^ (brow & 7)) * 16);
    }

    auto load_stage = [&](int c, int s) {
        const uint32_t so = s * STAGE_BYTES;
        const __half* sa = srcA + c * 64;
        #pragma unroll
        for (int g = 0; g < 4; g++)
            cp_async16(dstA[g] + so, sa + g * 8);
        if (loadB) {
            const __half* sb = srcB + c * 64;
            #pragma unroll
            for (int g = 0; g < 4; g++)
                cp_async16(dstB[g] + so, sb + g * 8);
        }
    };

    float acc[4][4][4];
    #pragma unroll
    for (int mt = 0; mt < 4; mt++)
        #pragma unroll
        for (int nt = 0; nt < 4; nt++)
            #pragma unroll
            for (int j = 0; j < 4; j++)
                acc[mt][nt][j] = 0.f;

    #pragma unroll
    for (int c = 0; c < NST - 1; c++) {
        load_stage(c, c);
        CP_COMMIT();
    }

    const int arow_l = (lane & 15);
    const int agrp_l = (lane >> 4);
    const int brow_l = (lane & 7) + ((lane >> 4) << 3);
    const int bgrp_l = (lane >> 3) & 1;

    for (int c = 0; c < nk; c++) {
        CP_WAIT(NST - 2);
        __syncthreads();
        if (c + NST - 1 < nk)
            load_stage(c + NST - 1, (c + NST - 1) % NST);
        CP_COMMIT();

        const uint32_t aB = smBase + (c % NST) * STAGE_BYTES;
        const uint32_t bB = aB + A_BYTES;

        #pragma unroll
        for (int ks = 0; ks < 4; ks++) {
            const int agH = ks * 2 + agrp_l;
            const int bgH = ks * 2 + bgrp_l;

            uint32_t bf[2][4];
            #pragma unroll
            for (int np = 0; np < 2; np++) {
                const int r = wn + np * 16 + brow_l;
                ldsm_x4(bf[np], bB + r * 128 + ((bgH ^ (r & 7)) * 16));
            }

            #pragma unroll
            for (int mt = 0; mt < 4; mt++) {
                const int r = wm + mt * 16 + arow_l;
                uint32_t af[4];
                ldsm_x4(af, aB + r * 128 + ((agH ^ (r & 7)) * 16));
                #pragma unroll
                for (int nt = 0; nt < 4; nt++) {
                    const int np = nt >> 1, o = (nt & 1) * 2;
                    mma_f16(acc[mt][nt], af, bf[np][o], bf[np][o + 1]);
                }
            }
        }
    }

    const int r0 = lane >> 2;
    const int c0 = (lane & 3) * 2;

    #pragma unroll
    for (int mt = 0; mt < 4; mt++) {
        #pragma unroll
        for (int h = 0; h < 2; h++) {
            const int row_o = m0 + wm + mt * 16 + h * 8 + r0;
            __half* op = outHi + (size_t)row_o * H_ + n0 + wn + c0;
            #pragma unroll
            for (int nt = 0; nt < 4; nt++) {
                float vx = acc[mt][nt][h * 2 + 0];
                float vy = acc[mt][nt][h * 2 + 1];
                if (RELU_BIAS) {
                    const int gc = n0 + wn + nt * 8 + c0;
                    vx = fmaxf(vx + bias[gc], 0.f);
                    vy = fmaxf(vy + bias[gc + 1], 0.f);
                }
                *(__half2*)(op + nt * 8) =
                    __halves2half2(__float2half_rn(vx), __float2half_rn(vy));
            }
        }
    }
}

// ============================================================================
// Local windowed attention — BOTH phases on HMMA.
// Per block (b, 16 s): hs[48][1024] fp16 resident (pitch 1032 halves, row
// bank-offset 4 -> conflict-free ldsm).
//   Phase A: D[16x48] = Q @ Hs^T.  6 warps = 3 j-tiles(16) x 2 k-halves(512);
//            Q A-fragments via direct LDG; B via non-trans ldsm (hs = [N,K]).
//   Softmax: 16 threads; P'[s][j] fp16, zero outside band j in [s, s+32].
//   Phase C: Out[16x1024] = P'[16x48] @ Hs.  8 warps x 128 cols; A via ldsm
//            on ps (pitch 72), B via TRANS ldsm on hs k-rows.
// ============================================================================
#define TS 16
#define HPH 1032                          // hs pitch (halves)
#define HROWB (HPH * 2)                   // 2064 bytes
#define HSB (48 * HROWB)                  // 99072
#define SCF_OFF HSB                       // 16 x 52 fp32 = 3328
#define DRED_OFF (SCF_OFF + 16 * 52 * 4)  // 3 x 16 x 16 fp32 = 3072
#define PS_OFF (DRED_OFF + 3072)          // 16 x 72 half = 2304
#define ATT_SMEM (PS_OFF + 2304)

__global__ __launch_bounds__(256, 2)
void atten_kernel(const __half* __restrict__ hh, const __half* __restrict__ qh,
                  float* __restrict__ out)
{
    extern __shared__ __align__(16) char asmem[];
    __half* hs = (__half*)asmem;
    float*  scf = (float*)(asmem + SCF_OFF);            // [16][52]
    float*  dred = (float*)(asmem + DRED_OFF);          // [3][16][16]
    __half* ps = (__half*)(asmem + PS_OFF);             // [16][72]
    const uint32_t sbase = smem_u32(asmem);

    const int tid = threadIdx.x;
    const int wid = tid >> 5, lane = tid & 31;
    const int b = blockIdx.y;
    const int s0 = blockIdx.x * TS;

    const __half* hB = hh + (size_t)b * S_ * H_;
    const __half* qB = qh + (size_t)b * S_ * H_;
    float*        oB = out + (size_t)b * S_ * H_;

    // ---- load 48 x 1024 fp16 neighborhood ----
    for (int i = tid; i < 48 * 128; i += 256) {
        const int r = i >> 7;
        const int c = (i & 127) * 8;
        const int g = s0 - 16 + r;
        uint4 v = make_uint4(0, 0, 0, 0);
        if (g >= 0 && g < S_)
            v = *(const uint4*)(hB + (size_t)g * H_ + c);
        *(uint4*)&hs[r * HPH + c] = v;
    }
    __syncthreads();

    const int r0 = lane >> 2;            // 0..7
    const int c0 = (lane & 3) * 2;
    const int brow_l = (lane & 7) + ((lane >> 4) << 3);
    const int bgrp_l = (lane >> 3) & 1;

    // ---------------- Phase A: D = Q @ Hs^T ----------------
    float d[2][4];
    #pragma unroll
    for (int np = 0; np < 2; np++)
        #pragma unroll
        for (int j = 0; j < 4; j++) d[np][j] = 0.f;

    const int nt = wid % 3;              // j-tile (16 wide)
    const int kh = wid / 3;              // k half
    if (wid < 6) {
        const int j0 = nt * 16;
        const uint32_t bbase = sbase + (j0 + brow_l) * HROWB + bgrp_l * 16;
        const __half* q0 = qB + (size_t)(s0 + r0) * H_ + kh * 512 + c0;
        #pragma unroll 4
        for (int ks = 0; ks < 32; ks++) {
            const int gk = kh * 32 + ks;
            uint32_t bf[4];
            ldsm_x4(bf, bbase + gk * 32);
            uint32_t a[4];
            const __half* qp = q0 + ks * 16;
            a[0] = *(const uint32_t*)(qp);
            a[1] = *(const uint32_t*)(qp + 8 * H_);
            a[2] = *(const uint32_t*)(qp + 8);
            a[3] = *(const uint32_t*)(qp + 8 * H_ + 8);
            mma_f16(d[0], a, bf[0], bf[1]);
            mma_f16(d[1], a, bf[2], bf[3]);
        }
        if (kh == 1) {
            float* dr = dred + nt * 256;
            #pragma unroll
            for (int np = 0; np < 2; np++) {
                *(float2*)&dr[r0 * 16 + np * 8 + c0] =
                    make_float2(d[np][0], d[np][1]);
                *(float2*)&dr[(r0 + 8) * 16 + np * 8 + c0] =
                    make_float2(d[np][2], d[np][3]);
            }
        }
    }
    __syncthreads();
    if (wid < 3) {
        const int j0 = nt * 16;
        const float* dr = dred + nt * 256;
        #pragma unroll
        for (int np = 0; np < 2; np++) {
            float2 p0 = *(const float2*)&dr[r0 * 16 + np * 8 + c0];
            float2 p1 = *(const float2*)&dr[(r0 + 8) * 16 + np * 8 + c0];
            scf[r0 * 52 + j0 + np * 8 + c0]     = d[np][0] + p0.x;
            scf[r0 * 52 + j0 + np * 8 + c0 + 1] = d[np][1] + p0.y;
            scf[(r0 + 8) * 52 + j0 + np * 8 + c0]     = d[np][2] + p1.x;
            scf[(r0 + 8) * 52 + j0 + np * 8 + c0 + 1] = d[np][3] + p1.y;
        }
    }
    __syncthreads();

    // ---------------- Softmax -> ps (fp16, banded) ----------------
    if (tid < TS) {
        const int s = tid;
        float m = -1e30f;
        for (int j = s; j <= s + 32; j++)
            m = fmaxf(m, scf[s * 52 + j]);
        m *= 0.03125f;
        float e[AW];
        float Z = 0.f;
        for (int j = 0; j < AW; j++) {
            e[j] = expf(scf[s * 52 + s + j] * 0.03125f - m);
            Z += e[j];
        }
        const float inv = 1.f / Z;
        for (int j = 0; j < 48; j++) {
            float v = (j >= s && j <= s + 32) ? e[j - s] * inv : 0.f;
            ps[s * 72 + j] = __float2half_rn(v);
        }
        // pad cols 48..71 once (ldsm only reads 0..47, keep deterministic)
        for (int j = 48; j < 72; j++) ps[s * 72 + j] = __float2half_rn(0.f);
    }
    __syncthreads();

    // ---------------- Phase C: Out = P' @ Hs ----------------
    // A fragments from ps (pitch 144B)
    uint32_t pa[3][4];
    #pragma unroll
    for (int ks = 0; ks < 3; ks++) {
        const uint32_t aaddr = sbase + PS_OFF + (lane & 15) * 144
                             + (ks * 2 + (lane >> 4)) * 16;
        ldsm_x4(pa[ks], aaddr);
    }

    const int n0w = wid * 128;
    const int krl = (lane & 7) + (((lane >> 3) & 1) << 3);   // k row within 16
    const int ncl = (lane >> 4) << 3;                         // 0 or 8

    #pragma unroll
    for (int gci = 0; gci < 8; gci++) {
        const int n0 = n0w + gci * 16;
        float o[2][4];
        #pragma unroll
        for (int np = 0; np < 2; np++)
            #pragma unroll
            for (int j = 0; j < 4; j++) o[np][j] = 0.f;

        #pragma unroll
        for (int ks = 0; ks < 3; ks++) {
            uint32_t bf[4];
            ldsm_x4_t(bf, sbase + (ks * 16 + krl) * HROWB + (n0 + ncl) * 2);
            mma_f16(o[0], pa[ks], bf[0], bf[1]);
            mma_f16(o[1], pa[ks], bf[2], bf[3]);
        }
        #pragma unroll
        for (int np = 0; np < 2; np++) {
            float* p0 = oB + (size_t)(s0 + r0) * H_ + n0 + np * 8 + c0;
            float* p1 = oB + (size_t)(s0 + r0 + 8) * H_ + n0 + np * 8 + c0;
            *(float2*)p0 = make_float2(o[np][0], o[np][1]);
            *(float2*)p1 = make_float2(o[np][2], o[np][3]);
        }
    }
}

// ============================================================================
// Launch
// ============================================================================
extern "C" void kernel_launch(void* const* d_in, const int* in_sizes, int n_in,
                              void* d_out, int out_size)
{
    const float* x  = (const float*)d_in[0];   // [4,2048,512]
    const float* W1 = (const float*)d_in[1];   // [512,1024]
    const float* b1 = (const float*)d_in[2];   // [1024]
    const float* Wq = (const float*)d_in[3];   // [1024,1024]
    float* out = (float*)d_out;                // [4,2048,1024]

    __half *xhi, *hhi, *qhi, *w1thi, *wqthi;
    cudaGetSymbolAddress((void**)&xhi, g_xhi);
    cudaGetSymbolAddress((void**)&hhi, g_hhi);
    cudaGetSymbolAddress((void**)&qhi, g_qhi);
    cudaGetSymbolAddress((void**)&w1thi, g_w1t_hi);
    cudaGetSymbolAddress((void**)&wqthi, g_wqt_hi);

    cudaFuncSetAttribute((const void*)hmma_gemm<true>,
                         cudaFuncAttributeMaxDynamicSharedMemorySize, GEMM_SMEM);
    cudaFuncSetAttribute((const void*)hmma_gemm<false>,
                         cudaFuncAttributeMaxDynamicSharedMemorySize, GEMM_SMEM);
    cudaFuncSetAttribute((const void*)atten_kernel,
                         cudaFuncAttributeMaxDynamicSharedMemorySize, ATT_SMEM);

    // Converts
    {
        int n4 = M_ * IN_ / 4;
        split_hi_kernel<<<(n4 + 255) / 256, 256>>>(x, xhi, n4);
        dim3 t(32, 8);
        transpose_both_kernel<<<dim3(32, 48), t>>>(W1, w1thi, Wq, wqthi);
    }

    // GEMM1: hhi = fp16(relu(xhi @ W1hi + b1))
    {
        dim3 grid(H_ / 128, M_ / 256);
        hmma_gemm<true><<<grid, 512, GEMM_SMEM>>>(xhi, w1thi, b1, hhi, IN_);
    }
    // GEMM2: qhi = fp16(hhi @ Wqhi)
    {
        dim3 grid(H_ / 128, M_ / 256);
        hmma_gemm<false><<<grid, 512, GEMM_SMEM>>>(hhi, wqthi, nullptr, qhi, H_);
    }
    // Attention (HMMA both phases)
    {
        dim3 grid(S_ / TS, B_);
        atten_kernel<<<grid, 256, ATT_SMEM>>>(hhi, qhi, out);
    }
}

// round 16
// speedup vs baseline: 1.7779x; 1.0694x over previous
#include <cuda_runtime.h>
#include <cuda_fp16.h>
#include <math.h>
#include <stdint.h>

// ============================================================================
// Problem constants
// ============================================================================
#define B_   4
#define S_   2048
#define IN_  512
#define H_   1024
#define M_   (B_ * S_)   // 8192
#define AW   33          // 2*atten_size + 1

// ============================================================================
// Device global scratch (allocation-free per harness rules)
// ============================================================================
__device__ __half g_xhi[(size_t)M_ * IN_];
__device__ __half g_hhi[(size_t)M_ * H_];
__device__ __half g_qhi[(size_t)M_ * H_];
__device__ __half g_w1t_hi[(size_t)H_ * IN_];   // W1^T [1024,512]
__device__ __half g_wqt_hi[(size_t)H_ * H_];    // Wq^T [1024,1024]

// ============================================================================
// PTX helpers (base sm_103 ISA only: cp.async, ldmatrix, mma.sync)
// ============================================================================
__device__ __forceinline__ uint32_t smem_u32(const void* p) {
    uint32_t a;
    asm("{ .reg .u64 t; cvta.to.shared.u64 t, %1; cvt.u32.u64 %0, t; }"
        : "=r"(a) : "l"(p));
    return a;
}

__device__ __forceinline__ void cp_async16(uint32_t dst, const void* src) {
    asm volatile("cp.async.cg.shared.global [%0], [%1], 16;"
                 :: "r"(dst), "l"(src));
}
#define CP_COMMIT() asm volatile("cp.async.commit_group;" ::: "memory")
#define CP_WAIT(n)  asm volatile("cp.async.wait_group %0;" :: "n"(n) : "memory")

__device__ __forceinline__ void ldsm_x4(uint32_t* r, uint32_t addr) {
    asm volatile("ldmatrix.sync.aligned.m8n8.x4.shared.b16 {%0,%1,%2,%3}, [%4];"
                 : "=r"(r[0]), "=r"(r[1]), "=r"(r[2]), "=r"(r[3]) : "r"(addr));
}
__device__ __forceinline__ void ldsm_x4_t(uint32_t* r, uint32_t addr) {
    asm volatile("ldmatrix.sync.aligned.m8n8.x4.trans.shared.b16 {%0,%1,%2,%3}, [%4];"
                 : "=r"(r[0]), "=r"(r[1]), "=r"(r[2]), "=r"(r[3]) : "r"(addr));
}

__device__ __forceinline__ void mma_f16(float* c, const uint32_t* a,
                                        uint32_t b0, uint32_t b1) {
    asm volatile(
        "mma.sync.aligned.m16n8k16.row.col.f32.f16.f16.f32 "
        "{%0,%1,%2,%3}, {%4,%5,%6,%7}, {%8,%9}, {%0,%1,%2,%3};"
        : "+f"(c[0]), "+f"(c[1]), "+f"(c[2]), "+f"(c[3])
        : "r"(a[0]), "r"(a[1]), "r"(a[2]), "r"(a[3]), "r"(b0), "r"(b1));
}

// ============================================================================
// Merged convert kernel:
//   blocks [0, NB_SPLIT)                : x fp32 -> fp16
//   blocks [NB_SPLIT, +512)             : W1 transpose+convert
//   blocks [NB_SPLIT+512, +1024)        : Wq transpose+convert
// ============================================================================
#define NB_SPLIT (M_ * IN_ / 4 / 256)    // 4096

__global__ __launch_bounds__(256)
void convert_all_kernel(const float* __restrict__ x, __half* __restrict__ xhi,
                        const float* __restrict__ W1, __half* __restrict__ w1T,
                        const float* __restrict__ Wq, __half* __restrict__ wqT)
{
    const int bid = blockIdx.x;
    const int tid = threadIdx.x;

    if (bid < NB_SPLIT) {
        const int i = bid * 256 + tid;
        float4 v = ((const float4*)x)[i];
        ((__half2*)xhi)[i * 2 + 0] = __halves2half2(__float2half_rn(v.x),
                                                    __float2half_rn(v.y));
        ((__half2*)xhi)[i * 2 + 1] = __halves2half2(__float2half_rn(v.z),
                                                    __float2half_rn(v.w));
        return;
    }

    __shared__ float t[32][33];
    const int b2 = bid - NB_SPLIT;
    const bool isW1 = (b2 < 512);
    const float* in = isW1 ? W1 : Wq;
    __half* outT = isW1 ? w1T : wqT;
    const int R = isW1 ? IN_ : H_;
    const int b3 = isW1 ? b2 : (b2 - 512);
    const int c0 = (b3 & 31) * 32;
    const int r0 = (b3 >> 5) * 32;
    const int tx = tid & 31, ty = tid >> 5;   // 32 x 8
    #pragma unroll
    for (int j = 0; j < 32; j += 8)
        t[ty + j][tx] = in[(size_t)(r0 + ty + j) * H_ + c0 + tx];
    __syncthreads();
    #pragma unroll
    for (int j = 0; j < 32; j += 8)
        outT[(size_t)(c0 + ty + j) * R + r0 + tx] = __float2half_rn(t[tx][ty + j]);
}

// ============================================================================
// HMMA GEMM (fp32 accum, fp16) — proven config; loader B rebalanced over all
// 512 threads (2 groups each).
// Block tile 256x128, BK=64/stage, 16 warps (warp tile 64x32), NST=4.
// ============================================================================
#define NST 4
#define A_BYTES 32768
#define STAGE_BYTES (A_BYTES + 16384)
#define GEMM_SMEM (NST * STAGE_BYTES)    // 192 KB

template <bool RELU_BIAS>
__global__ __launch_bounds__(512, 1)
void hmma_gemm(const __half* __restrict__ Ahi,
               const __half* __restrict__ Bhi,
               const float* __restrict__ bias,
               __half* __restrict__ outHi,
               int K)
{
    extern __shared__ __align__(1024) char smem[];
    const uint32_t smBase = smem_u32(smem);

    const int tid  = threadIdx.x;
    const int wid  = tid >> 5;
    const int lane = tid & 31;
    const int m0 = blockIdx.y * 256;
    const int n0 = blockIdx.x * 128;
    const int nk = K / 64;

    const int wm = (wid & 3) * 64;
    const int wn = (wid >> 2) * 32;

    // A: thread = k-half (0/32) of one of 256 rows (4 groups)
    const int half_sel = tid & 1;
    const int arow = tid >> 1;
    const __half* srcA = Ahi + (size_t)(m0 + arow) * K + half_sel * 32;
    uint32_t dstA[4];
    #pragma unroll
    for (int g = 0; g < 4; g++) {
        const int lg = half_sel * 4 + g;
        dstA[g] = smBase + arow * 128 + ((lg ^ (arow & 7)) * 16);
    }
    // B: thread = 2 of 8 groups of one of 128 rows
    const int brow = tid >> 2;
    const int bg0 = (tid & 3) * 2;
    const __half* srcB = Bhi + (size_t)(n0 + brow) * K + bg0 * 8;
    uint32_t dstB[2];
    #pragma unroll
    for (int g = 0; g < 2; g++) {
        const int lg = bg0 + g;
        dstB[g] = smBase + A_BYTES + brow * 128 + ((lg ^ (brow & 7)) * 16);
    }

    auto load_stage = [&](int c, int s) {
        const uint32_t so = s * STAGE_BYTES;
        const __half* sa = srcA + c * 64;
        #pragma unroll
        for (int g = 0; g < 4; g++)
            cp_async16(dstA[g] + so, sa + g * 8);
        const __half* sb = srcB + c * 64;
        #pragma unroll
        for (int g = 0; g < 2; g++)
            cp_async16(dstB[g] + so, sb + g * 8);
    };

    float acc[4][4][4];
    #pragma unroll
    for (int mt = 0; mt < 4; mt++)
        #pragma unroll
        for (int nt = 0; nt < 4; nt++)
            #pragma unroll
            for (int j = 0; j < 4; j++)
                acc[mt][nt][j] = 0.f;

    #pragma unroll
    for (int c = 0; c < NST - 1; c++) {
        load_stage(c, c);
        CP_COMMIT();
    }

    const int arow_l = (lane & 15);
    const int agrp_l = (lane >> 4);
    const int brow_l = (lane & 7) + ((lane >> 4) << 3);
    const int bgrp_l = (lane >> 3) & 1;

    for (int c = 0; c < nk; c++) {
        CP_WAIT(NST - 2);
        __syncthreads();
        if (c + NST - 1 < nk)
            load_stage(c + NST - 1, (c + NST - 1) % NST);
        CP_COMMIT();

        const uint32_t aB = smBase + (c % NST) * STAGE_BYTES;
        const uint32_t bB = aB + A_BYTES;

        #pragma unroll
        for (int ks = 0; ks < 4; ks++) {
            const int agH = ks * 2 + agrp_l;
            const int bgH = ks * 2 + bgrp_l;

            uint32_t bf[2][4];
            #pragma unroll
            for (int np = 0; np < 2; np++) {
                const int r = wn + np * 16 + brow_l;
                ldsm_x4(bf[np], bB + r * 128 + ((bgH ^ (r & 7)) * 16));
            }

            #pragma unroll
            for (int mt = 0; mt < 4; mt++) {
                const int r = wm + mt * 16 + arow_l;
                uint32_t af[4];
                ldsm_x4(af, aB + r * 128 + ((agH ^ (r & 7)) * 16));
                #pragma unroll
                for (int nt = 0; nt < 4; nt++) {
                    const int np = nt >> 1, o = (nt & 1) * 2;
                    mma_f16(acc[mt][nt], af, bf[np][o], bf[np][o + 1]);
                }
            }
        }
    }

    const int r0 = lane >> 2;
    const int c0 = (lane & 3) * 2;

    #pragma unroll
    for (int mt = 0; mt < 4; mt++) {
        #pragma unroll
        for (int h = 0; h < 2; h++) {
            const int row_o = m0 + wm + mt * 16 + h * 8 + r0;
            __half* op = outHi + (size_t)row_o * H_ + n0 + wn + c0;
            #pragma unroll
            for (int nt = 0; nt < 4; nt++) {
                float vx = acc[mt][nt][h * 2 + 0];
                float vy = acc[mt][nt][h * 2 + 1];
                if (RELU_BIAS) {
                    const int gc = n0 + wn + nt * 8 + c0;
                    vx = fmaxf(vx + bias[gc], 0.f);
                    vy = fmaxf(vy + bias[gc + 1], 0.f);
                }
                *(__half2*)(op + nt * 8) =
                    __halves2half2(__float2half_rn(vx), __float2half_rn(vy));
            }
        }
    }
}

// ============================================================================
// Local windowed attention — BOTH phases on HMMA (round-15 proven), with
// cp.async hs tile load.
// ============================================================================
#define TS 16
#define HPH 1032                          // hs pitch (halves)
#define HROWB (HPH * 2)                   // 2064 bytes
#define HSB (48 * HROWB)                  // 99072
#define SCF_OFF HSB                       // 16 x 52 fp32 = 3328
#define DRED_OFF (SCF_OFF + 16 * 52 * 4)  // 3 x 16 x 16 fp32 = 3072
#define PS_OFF (DRED_OFF + 3072)          // 16 x 72 half = 2304
#define ATT_SMEM (PS_OFF + 2304)

__global__ __launch_bounds__(256, 2)
void atten_kernel(const __half* __restrict__ hh, const __half* __restrict__ qh,
                  float* __restrict__ out)
{
    extern __shared__ __align__(16) char asmem[];
    __half* hs = (__half*)asmem;
    float*  scf = (float*)(asmem + SCF_OFF);            // [16][52]
    float*  dred = (float*)(asmem + DRED_OFF);          // [3][16][16]
    __half* ps = (__half*)(asmem + PS_OFF);             // [16][72]
    const uint32_t sbase = smem_u32(asmem);

    const int tid = threadIdx.x;
    const int wid = tid >> 5, lane = tid & 31;
    const int b = blockIdx.y;
    const int s0 = blockIdx.x * TS;

    const __half* hB = hh + (size_t)b * S_ * H_;
    const __half* qB = qh + (size_t)b * S_ * H_;
    float*        oB = out + (size_t)b * S_ * H_;

    // ---- load 48 x 1024 fp16 neighborhood (cp.async; zero-fill OOB) ----
    for (int i = tid; i < 48 * 128; i += 256) {
        const int r = i >> 7;
        const int c = (i & 127) * 8;
        const int g = s0 - 16 + r;
        if (g >= 0 && g < S_)
            cp_async16(sbase + r * HROWB + c * 2, hB + (size_t)g * H_ + c);
        else
            *(uint4*)&hs[r * HPH + c] = make_uint4(0, 0, 0, 0);
    }
    CP_COMMIT();
    CP_WAIT(0);
    __syncthreads();

    const int r0 = lane >> 2;            // 0..7
    const int c0 = (lane & 3) * 2;
    const int brow_l = (lane & 7) + ((lane >> 4) << 3);
    const int bgrp_l = (lane >> 3) & 1;

    // ---------------- Phase A: D = Q @ Hs^T ----------------
    float d[2][4];
    #pragma unroll
    for (int np = 0; np < 2; np++)
        #pragma unroll
        for (int j = 0; j < 4; j++) d[np][j] = 0.f;

    const int nt = wid % 3;              // j-tile (16 wide)
    const int kh = wid / 3;              // k half
    if (wid < 6) {
        const int j0 = nt * 16;
        const uint32_t bbase = sbase + (j0 + brow_l) * HROWB + bgrp_l * 16;
        const __half* q0 = qB + (size_t)(s0 + r0) * H_ + kh * 512 + c0;
        #pragma unroll 4
        for (int ks = 0; ks < 32; ks++) {
            const int gk = kh * 32 + ks;
            uint32_t bf[4];
            ldsm_x4(bf, bbase + gk * 32);
            uint32_t a[4];
            const __half* qp = q0 + ks * 16;
            a[0] = *(const uint32_t*)(qp);
            a[1] = *(const uint32_t*)(qp + 8 * H_);
            a[2] = *(const uint32_t*)(qp + 8);
            a[3] = *(const uint32_t*)(qp + 8 * H_ + 8);
            mma_f16(d[0], a, bf[0], bf[1]);
            mma_f16(d[1], a, bf[2], bf[3]);
        }
        if (kh == 1) {
            float* dr = dred + nt * 256;
            #pragma unroll
            for (int np = 0; np < 2; np++) {
                *(float2*)&dr[r0 * 16 + np * 8 + c0] =
                    make_float2(d[np][0], d[np][1]);
                *(float2*)&dr[(r0 + 8) * 16 + np * 8 + c0] =
                    make_float2(d[np][2], d[np][3]);
            }
        }
    }
    __syncthreads();
    if (wid < 3) {
        const int j0 = nt * 16;
        const float* dr = dred + nt * 256;
        #pragma unroll
        for (int np = 0; np < 2; np++) {
            float2 p0 = *(const float2*)&dr[r0 * 16 + np * 8 + c0];
            float2 p1 = *(const float2*)&dr[(r0 + 8) * 16 + np * 8 + c0];
            scf[r0 * 52 + j0 + np * 8 + c0]     = d[np][0] + p0.x;
            scf[r0 * 52 + j0 + np * 8 + c0 + 1] = d[np][1] + p0.y;
            scf[(r0 + 8) * 52 + j0 + np * 8 + c0]     = d[np][2] + p1.x;
            scf[(r0 + 8) * 52 + j0 + np * 8 + c0 + 1] = d[np][3] + p1.y;
        }
    }
    __syncthreads();

    // ---------------- Softmax -> ps (fp16, banded) ----------------
    if (tid < TS) {
        const int s = tid;
        float m = -1e30f;
        for (int j = s; j <= s + 32; j++)
            m = fmaxf(m, scf[s * 52 + j]);
        m *= 0.03125f;
        float e[AW];
        float Z = 0.f;
        for (int j = 0; j < AW; j++) {
            e[j] = expf(scf[s * 52 + s + j] * 0.03125f - m);
            Z += e[j];
        }
        const float inv = 1.f / Z;
        for (int j = 0; j < 48; j++) {
            float v = (j >= s && j <= s + 32) ? e[j - s] * inv : 0.f;
            ps[s * 72 + j] = __float2half_rn(v);
        }
        for (int j = 48; j < 72; j++) ps[s * 72 + j] = __float2half_rn(0.f);
    }
    __syncthreads();

    // ---------------- Phase C: Out = P' @ Hs ----------------
    uint32_t pa[3][4];
    #pragma unroll
    for (int ks = 0; ks < 3; ks++) {
        const uint32_t aaddr = sbase + PS_OFF + (lane & 15) * 144
                             + (ks * 2 + (lane >> 4)) * 16;
        ldsm_x4(pa[ks], aaddr);
    }

    const int n0w = wid * 128;
    const int krl = (lane & 7) + (((lane >> 3) & 1) << 3);
    const int ncl = (lane >> 4) << 3;

    #pragma unroll
    for (int gci = 0; gci < 8; gci++) {
        const int n0 = n0w + gci * 16;
        float o[2][4];
        #pragma unroll
        for (int np = 0; np < 2; np++)
            #pragma unroll
            for (int j = 0; j < 4; j++) o[np][j] = 0.f;

        #pragma unroll
        for (int ks = 0; ks < 3; ks++) {
            uint32_t bf[4];
            ldsm_x4_t(bf, sbase + (ks * 16 + krl) * HROWB + (n0 + ncl) * 2);
            mma_f16(o[0], pa[ks], bf[0], bf[1]);
            mma_f16(o[1], pa[ks], bf[2], bf[3]);
        }
        #pragma unroll
        for (int np = 0; np < 2; np++) {
            float* p0 = oB + (size_t)(s0 + r0) * H_ + n0 + np * 8 + c0;
            float* p1 = oB + (size_t)(s0 + r0 + 8) * H_ + n0 + np * 8 + c0;
            *(float2*)p0 = make_float2(o[np][0], o[np][1]);
            *(float2*)p1 = make_float2(o[np][2], o[np][3]);
        }
    }
}

// ============================================================================
// Launch
// ============================================================================
extern "C" void kernel_launch(void* const* d_in, const int* in_sizes, int n_in,
                              void* d_out, int out_size)
{
    const float* x  = (const float*)d_in[0];   // [4,2048,512]
    const float* W1 = (const float*)d_in[1];   // [512,1024]
    const float* b1 = (const float*)d_in[2];   // [1024]
    const float* Wq = (const float*)d_in[3];   // [1024,1024]
    float* out = (float*)d_out;                // [4,2048,1024]

    __half *xhi, *hhi, *qhi, *w1thi, *wqthi;
    cudaGetSymbolAddress((void**)&xhi, g_xhi);
    cudaGetSymbolAddress((void**)&hhi, g_hhi);
    cudaGetSymbolAddress((void**)&qhi, g_qhi);
    cudaGetSymbolAddress((void**)&w1thi, g_w1t_hi);
    cudaGetSymbolAddress((void**)&wqthi, g_wqt_hi);

    cudaFuncSetAttribute((const void*)hmma_gemm<true>,
                         cudaFuncAttributeMaxDynamicSharedMemorySize, GEMM_SMEM);
    cudaFuncSetAttribute((const void*)hmma_gemm<false>,
                         cudaFuncAttributeMaxDynamicSharedMemorySize, GEMM_SMEM);
    cudaFuncSetAttribute((const void*)atten_kernel,
                         cudaFuncAttributeMaxDynamicSharedMemorySize, ATT_SMEM);

    // Converts (single launch: x split + W1^T + Wq^T)
    convert_all_kernel<<<NB_SPLIT + 512 + 1024, 256>>>(
        x, xhi, W1, w1thi, Wq, wqthi);

    // GEMM1: hhi = fp16(relu(xhi @ W1hi + b1))
    {
        dim3 grid(H_ / 128, M_ / 256);
        hmma_gemm<true><<<grid, 512, GEMM_SMEM>>>(xhi, w1thi, b1, hhi, IN_);
    }
    // GEMM2: qhi = fp16(hhi @ Wqhi)
    {
        dim3 grid(H_ / 128, M_ / 256);
        hmma_gemm<false><<<grid, 512, GEMM_SMEM>>>(hhi, wqthi, nullptr, qhi, H_);
    }
    // Attention (HMMA both phases)
    {
        dim3 grid(S_ / TS, B_);
        atten_kernel<<<grid, 256, ATT_SMEM>>>(hhi, qhi, out);
    }
}

// round 17
// speedup vs baseline: 1.9053x; 1.0717x over previous
#include <cuda_runtime.h>
#include <cuda_fp16.h>
#include <math.h>
#include <stdint.h>

// ============================================================================
// Problem constants
// ============================================================================
#define B_   4
#define S_   2048
#define IN_  512
#define H_   1024
#define M_   (B_ * S_)   // 8192
#define AW   33          // 2*atten_size + 1

// ============================================================================
// Device global scratch (allocation-free per harness rules)
// ============================================================================
__device__ __half g_xhi[(size_t)M_ * IN_];
__device__ __half g_hhi[(size_t)M_ * H_];
__device__ __half g_qhi[(size_t)M_ * H_];
__device__ __half g_w1t_hi[(size_t)H_ * IN_];   // W1^T [1024,512]
__device__ __half g_wqt_hi[(size_t)H_ * H_];    // Wq^T [1024,1024]

// ============================================================================
// PTX helpers (base sm_103 ISA only: cp.async, ldmatrix, mma.sync)
// ============================================================================
__device__ __forceinline__ uint32_t smem_u32(const void* p) {
    uint32_t a;
    asm("{ .reg .u64 t; cvta.to.shared.u64 t, %1; cvt.u32.u64 %0, t; }"
        : "=r"(a) : "l"(p));
    return a;
}

__device__ __forceinline__ void cp_async16(uint32_t dst, const void* src) {
    asm volatile("cp.async.cg.shared.global [%0], [%1], 16;"
                 :: "r"(dst), "l"(src));
}
#define CP_COMMIT() asm volatile("cp.async.commit_group;" ::: "memory")
#define CP_WAIT(n)  asm volatile("cp.async.wait_group %0;" :: "n"(n) : "memory")

__device__ __forceinline__ void ldsm_x4(uint32_t* r, uint32_t addr) {
    asm volatile("ldmatrix.sync.aligned.m8n8.x4.shared.b16 {%0,%1,%2,%3}, [%4];"
                 : "=r"(r[0]), "=r"(r[1]), "=r"(r[2]), "=r"(r[3]) : "r"(addr));
}
__device__ __forceinline__ void ldsm_x4_t(uint32_t* r, uint32_t addr) {
    asm volatile("ldmatrix.sync.aligned.m8n8.x4.trans.shared.b16 {%0,%1,%2,%3}, [%4];"
                 : "=r"(r[0]), "=r"(r[1]), "=r"(r[2]), "=r"(r[3]) : "r"(addr));
}

__device__ __forceinline__ void mma_f16(float* c, const uint32_t* a,
                                        uint32_t b0, uint32_t b1) {
    asm volatile(
        "mma.sync.aligned.m16n8k16.row.col.f32.f16.f16.f32 "
        "{%0,%1,%2,%3}, {%4,%5,%6,%7}, {%8,%9}, {%0,%1,%2,%3};"
        : "+f"(c[0]), "+f"(c[1]), "+f"(c[2]), "+f"(c[3])
        : "r"(a[0]), "r"(a[1]), "r"(a[2]), "r"(a[3]), "r"(b0), "r"(b1));
}

// ============================================================================
// Merged convert kernel (round-16 proven)
// ============================================================================
#define NB_SPLIT (M_ * IN_ / 4 / 256)    // 4096

__global__ __launch_bounds__(256)
void convert_all_kernel(const float* __restrict__ x, __half* __restrict__ xhi,
                        const float* __restrict__ W1, __half* __restrict__ w1T,
                        const float* __restrict__ Wq, __half* __restrict__ wqT)
{
    const int bid = blockIdx.x;
    const int tid = threadIdx.x;

    if (bid < NB_SPLIT) {
        const int i = bid * 256 + tid;
        float4 v = ((const float4*)x)[i];
        ((__half2*)xhi)[i * 2 + 0] = __halves2half2(__float2half_rn(v.x),
                                                    __float2half_rn(v.y));
        ((__half2*)xhi)[i * 2 + 1] = __halves2half2(__float2half_rn(v.z),
                                                    __float2half_rn(v.w));
        return;
    }

    __shared__ float t[32][33];
    const int b2 = bid - NB_SPLIT;
    const bool isW1 = (b2 < 512);
    const float* in = isW1 ? W1 : Wq;
    __half* outT = isW1 ? w1T : wqT;
    const int R = isW1 ? IN_ : H_;
    const int b3 = isW1 ? b2 : (b2 - 512);
    const int c0 = (b3 & 31) * 32;
    const int r0 = (b3 >> 5) * 32;
    const int tx = tid & 31, ty = tid >> 5;
    #pragma unroll
    for (int j = 0; j < 32; j += 8)
        t[ty + j][tx] = in[(size_t)(r0 + ty + j) * H_ + c0 + tx];
    __syncthreads();
    #pragma unroll
    for (int j = 0; j < 32; j += 8)
        outT[(size_t)(c0 + ty + j) * R + r0 + tx] = __float2half_rn(t[tx][ty + j]);
}

// ============================================================================
// HMMA GEMM (round-16 proven)
// ============================================================================
#define NST 4
#define A_BYTES 32768
#define STAGE_BYTES (A_BYTES + 16384)
#define GEMM_SMEM (NST * STAGE_BYTES)    // 192 KB

template <bool RELU_BIAS>
__global__ __launch_bounds__(512, 1)
void hmma_gemm(const __half* __restrict__ Ahi,
               const __half* __restrict__ Bhi,
               const float* __restrict__ bias,
               __half* __restrict__ outHi,
               int K)
{
    extern __shared__ __align__(1024) char smem[];
    const uint32_t smBase = smem_u32(smem);

    const int tid  = threadIdx.x;
    const int wid  = tid >> 5;
    const int lane = tid & 31;
    const int m0 = blockIdx.y * 256;
    const int n0 = blockIdx.x * 128;
    const int nk = K / 64;

    const int wm = (wid & 3) * 64;
    const int wn = (wid >> 2) * 32;

    const int half_sel = tid & 1;
    const int arow = tid >> 1;
    const __half* srcA = Ahi + (size_t)(m0 + arow) * K + half_sel * 32;
    uint32_t dstA[4];
    #pragma unroll
    for (int g = 0; g < 4; g++) {
        const int lg = half_sel * 4 + g;
        dstA[g] = smBase + arow * 128 + ((lg ^ (arow & 7)) * 16);
    }
    const int brow = tid >> 2;
    const int bg0 = (tid & 3) * 2;
    const __half* srcB = Bhi + (size_t)(n0 + brow) * K + bg0 * 8;
    uint32_t dstB[2];
    #pragma unroll
    for (int g = 0; g < 2; g++) {
        const int lg = bg0 + g;
        dstB[g] = smBase + A_BYTES + brow * 128 + ((lg ^ (brow & 7)) * 16);
    }

    auto load_stage = [&](int c, int s) {
        const uint32_t so = s * STAGE_BYTES;
        const __half* sa = srcA + c * 64;
        #pragma unroll
        for (int g = 0; g < 4; g++)
            cp_async16(dstA[g] + so, sa + g * 8);
        const __half* sb = srcB + c * 64;
        #pragma unroll
        for (int g = 0; g < 2; g++)
            cp_async16(dstB[g] + so, sb + g * 8);
    };

    float acc[4][4][4];
    #pragma unroll
    for (int mt = 0; mt < 4; mt++)
        #pragma unroll
        for (int nt = 0; nt < 4; nt++)
            #pragma unroll
            for (int j = 0; j < 4; j++)
                acc[mt][nt][j] = 0.f;

    #pragma unroll
    for (int c = 0; c < NST - 1; c++) {
        load_stage(c, c);
        CP_COMMIT();
    }

    const int arow_l = (lane & 15);
    const int agrp_l = (lane >> 4);
    const int brow_l = (lane & 7) + ((lane >> 4) << 3);
    const int bgrp_l = (lane >> 3) & 1;

    for (int c = 0; c < nk; c++) {
        CP_WAIT(NST - 2);
        __syncthreads();
        if (c + NST - 1 < nk)
            load_stage(c + NST - 1, (c + NST - 1) % NST);
        CP_COMMIT();

        const uint32_t aB = smBase + (c % NST) * STAGE_BYTES;
        const uint32_t bB = aB + A_BYTES;

        #pragma unroll
        for (int ks = 0; ks < 4; ks++) {
            const int agH = ks * 2 + agrp_l;
            const int bgH = ks * 2 + bgrp_l;

            uint32_t bf[2][4];
            #pragma unroll
            for (int np = 0; np < 2; np++) {
                const int r = wn + np * 16 + brow_l;
                ldsm_x4(bf[np], bB + r * 128 + ((bgH ^ (r & 7)) * 16));
            }

            #pragma unroll
            for (int mt = 0; mt < 4; mt++) {
                const int r = wm + mt * 16 + arow_l;
                uint32_t af[4];
                ldsm_x4(af, aB + r * 128 + ((agH ^ (r & 7)) * 16));
                #pragma unroll
                for (int nt = 0; nt < 4; nt++) {
                    const int np = nt >> 1, o = (nt & 1) * 2;
                    mma_f16(acc[mt][nt], af, bf[np][o], bf[np][o + 1]);
                }
            }
        }
    }

    const int r0 = lane >> 2;
    const int c0 = (lane & 3) * 2;

    #pragma unroll
    for (int mt = 0; mt < 4; mt++) {
        #pragma unroll
        for (int h = 0; h < 2; h++) {
            const int row_o = m0 + wm + mt * 16 + h * 8 + r0;
            __half* op = outHi + (size_t)row_o * H_ + n0 + wn + c0;
            #pragma unroll
            for (int nt = 0; nt < 4; nt++) {
                float vx = acc[mt][nt][h * 2 + 0];
                float vy = acc[mt][nt][h * 2 + 1];
                if (RELU_BIAS) {
                    const int gc = n0 + wn + nt * 8 + c0;
                    vx = fmaxf(vx + bias[gc], 0.f);
                    vy = fmaxf(vy + bias[gc + 1], 0.f);
                }
                *(__half2*)(op + nt * 8) =
                    __halves2half2(__float2half_rn(vx), __float2half_rn(vy));
            }
        }
    }
}

// ============================================================================
// Attention, TS=32: both phases HMMA, q staged in smem, parallel softmax.
// smem: hs[64][1032]h (132KB) + qs[32][1032]h (66KB) + scf[32][68]f + ps[32][72]h
// Phase A: D[32x64] = Q@Hs^T.  8 warps = 2 m-tiles x 4 j-tiles, full k each.
// Phase C: Out[32x1024] = P'@Hs. 8 warps = 2 m-tiles x 4 col-quarters.
// ============================================================================
#define TS 32
#define HPH 1032
#define HROWB (HPH * 2)                    // 2064 B
#define HS_OFF 0
#define QS_OFF (64 * HROWB)                // 132096
#define SCF_OFF (QS_OFF + 32 * HROWB)      // 198144 ; [32][68] fp32
#define PS_OFF (SCF_OFF + 32 * 68 * 4)     // 206848 ; [32][72] half
#define ATT_SMEM (PS_OFF + 32 * 72 * 2)    // 211456

__global__ __launch_bounds__(256, 1)
void atten_kernel(const __half* __restrict__ hh, const __half* __restrict__ qh,
                  float* __restrict__ out)
{
    extern __shared__ __align__(16) char asmem[];
    float*  scf = (float*)(asmem + SCF_OFF);
    __half* ps = (__half*)(asmem + PS_OFF);
    const uint32_t sbase = smem_u32(asmem);

    const int tid = threadIdx.x;
    const int wid = tid >> 5, lane = tid & 31;
    const int b = blockIdx.y;
    const int s0 = blockIdx.x * TS;

    const __half* hB = hh + (size_t)b * S_ * H_;
    const __half* qB = qh + (size_t)b * S_ * H_;
    float*        oB = out + (size_t)b * S_ * H_;

    // ---- load hs (64 rows) + qs (32 rows) via cp.async; zero OOB ----
    for (int i = tid; i < 96 * 128; i += 256) {
        if (i < 64 * 128) {
            const int r = i >> 7;
            const int c = (i & 127) * 8;
            const int g = s0 - 16 + r;
            if (g >= 0 && g < S_)
                cp_async16(sbase + HS_OFF + r * HROWB + c * 2,
                           hB + (size_t)g * H_ + c);
            else
                *(uint4*)(asmem + HS_OFF + r * HROWB + c * 2) =
                    make_uint4(0, 0, 0, 0);
        } else {
            const int j = i - 64 * 128;
            const int r = j >> 7;
            const int c = (j & 127) * 8;
            cp_async16(sbase + QS_OFF + r * HROWB + c * 2,
                       qB + (size_t)(s0 + r) * H_ + c);
        }
    }
    CP_COMMIT();
    CP_WAIT(0);
    __syncthreads();

    const int r0 = lane >> 2;
    const int c0 = (lane & 3) * 2;
    const int arow_l = lane & 15;
    const int agrp_l = lane >> 4;
    const int brow_l = (lane & 7) + ((lane >> 4) << 3);
    const int bgrp_l = (lane >> 3) & 1;

    // ---------------- Phase A: D = Q @ Hs^T ----------------
    {
        const int mt = wid >> 2;          // 0/1: rows mt*16
        const int jt = wid & 3;           // 0..3: cols jt*16
        const uint32_t qbase = sbase + QS_OFF + (mt * 16 + arow_l) * HROWB;
        const uint32_t hbase = sbase + HS_OFF + (jt * 16 + brow_l) * HROWB;

        float d[2][4];
        #pragma unroll
        for (int np = 0; np < 2; np++)
            #pragma unroll
            for (int j = 0; j < 4; j++) d[np][j] = 0.f;

        #pragma unroll 8
        for (int ks = 0; ks < 64; ks++) {
            uint32_t af[4], bf[4];
            ldsm_x4(af, qbase + (ks * 2 + agrp_l) * 16);
            ldsm_x4(bf, hbase + (ks * 2 + bgrp_l) * 16);
            mma_f16(d[0], af, bf[0], bf[1]);
            mma_f16(d[1], af, bf[2], bf[3]);
        }

        #pragma unroll
        for (int np = 0; np < 2; np++) {
            const int col = jt * 16 + np * 8 + c0;
            *(float2*)&scf[(mt * 16 + r0) * 68 + col] =
                make_float2(d[np][0], d[np][1]);
            *(float2*)&scf[(mt * 16 + r0 + 8) * 68 + col] =
                make_float2(d[np][2], d[np][3]);
        }
    }
    __syncthreads();

    // ---------------- Softmax (32 groups x 8 lanes) -> ps ----------------
    {
        const int s = tid >> 3;           // 0..31
        const int l = tid & 7;
        const float scale = 0.03125f;     // 1/sqrt(1024)
        float m = -1e30f;
        #pragma unroll
        for (int mm = 0; mm < 5; mm++) {
            const int j = l + mm * 8;
            if (j <= 32) m = fmaxf(m, scf[s * 68 + s + j]);
        }
        #pragma unroll
        for (int dd = 4; dd >= 1; dd >>= 1)
            m = fmaxf(m, __shfl_xor_sync(0xffffffffu, m, dd));
        const float ms = m * scale;
        float Z = 0.f;
        #pragma unroll
        for (int mm = 0; mm < 5; mm++) {
            const int j = l + mm * 8;
            if (j <= 32) Z += expf(scf[s * 68 + s + j] * scale - ms);
        }
        #pragma unroll
        for (int dd = 4; dd >= 1; dd >>= 1)
            Z += __shfl_xor_sync(0xffffffffu, Z, dd);
        const float inv = 1.f / Z;
        #pragma unroll
        for (int mm = 0; mm < 9; mm++) {
            const int c = l + mm * 8;     // 0..71
            float v = 0.f;
            if (c >= s && c <= s + 32 && c < 64)
                v = expf(scf[s * 68 + c] * scale - ms) * inv;
            ps[s * 72 + c] = __float2half_rn(v);
        }
    }
    __syncthreads();

    // ---------------- Phase C: Out = P' @ Hs ----------------
    {
        const int mt = wid >> 2;          // rows mt*16
        const int cq = wid & 3;           // col quarter (256)
        uint32_t pa[4][4];
        #pragma unroll
        for (int ks = 0; ks < 4; ks++) {
            const uint32_t aaddr = sbase + PS_OFF
                                 + (mt * 16 + arow_l) * 144
                                 + (ks * 2 + agrp_l) * 16;
            ldsm_x4(pa[ks], aaddr);
        }

        const int krl = (lane & 7) + (((lane >> 3) & 1) << 3);
        const int ncl = (lane >> 4) << 3;

        #pragma unroll
        for (int gci = 0; gci < 16; gci++) {
            const int n0 = cq * 256 + gci * 16;
            float o[2][4];
            #pragma unroll
            for (int np = 0; np < 2; np++)
                #pragma unroll
                for (int j = 0; j < 4; j++) o[np][j] = 0.f;

            #pragma unroll
            for (int ks = 0; ks < 4; ks++) {
                uint32_t bf[4];
                ldsm_x4_t(bf, sbase + HS_OFF + (ks * 16 + krl) * HROWB
                              + (n0 + ncl) * 2);
                mma_f16(o[0], pa[ks], bf[0], bf[1]);
                mma_f16(o[1], pa[ks], bf[2], bf[3]);
            }
            #pragma unroll
            for (int np = 0; np < 2; np++) {
                float* p0 = oB + (size_t)(s0 + mt * 16 + r0) * H_
                          + n0 + np * 8 + c0;
                float* p1 = oB + (size_t)(s0 + mt * 16 + r0 + 8) * H_
                          + n0 + np * 8 + c0;
                *(float2*)p0 = make_float2(o[np][0], o[np][1]);
                *(float2*)p1 = make_float2(o[np][2], o[np][3]);
            }
        }
    }
}

// ============================================================================
// Launch
// ============================================================================
extern "C" void kernel_launch(void* const* d_in, const int* in_sizes, int n_in,
                              void* d_out, int out_size)
{
    const float* x  = (const float*)d_in[0];   // [4,2048,512]
    const float* W1 = (const float*)d_in[1];   // [512,1024]
    const float* b1 = (const float*)d_in[2];   // [1024]
    const float* Wq = (const float*)d_in[3];   // [1024,1024]
    float* out = (float*)d_out;                // [4,2048,1024]

    __half *xhi, *hhi, *qhi, *w1thi, *wqthi;
    cudaGetSymbolAddress((void**)&xhi, g_xhi);
    cudaGetSymbolAddress((void**)&hhi, g_hhi);
    cudaGetSymbolAddress((void**)&qhi, g_qhi);
    cudaGetSymbolAddress((void**)&w1thi, g_w1t_hi);
    cudaGetSymbolAddress((void**)&wqthi, g_wqt_hi);

    cudaFuncSetAttribute((const void*)hmma_gemm<true>,
                         cudaFuncAttributeMaxDynamicSharedMemorySize, GEMM_SMEM);
    cudaFuncSetAttribute((const void*)hmma_gemm<false>,
                         cudaFuncAttributeMaxDynamicSharedMemorySize, GEMM_SMEM);
    cudaFuncSetAttribute((const void*)atten_kernel,
                         cudaFuncAttributeMaxDynamicSharedMemorySize, ATT_SMEM);

    // Converts (single launch)
    convert_all_kernel<<<NB_SPLIT + 512 + 1024, 256>>>(
        x, xhi, W1, w1thi, Wq, wqthi);

    // GEMM1: hhi = fp16(relu(xhi @ W1hi + b1))
    {
        dim3 grid(H_ / 128, M_ / 256);
        hmma_gemm<true><<<grid, 512, GEMM_SMEM>>>(xhi, w1thi, b1, hhi, IN_);
    }
    // GEMM2: qhi = fp16(hhi @ Wqhi)
    {
        dim3 grid(H_ / 128, M_ / 256);
        hmma_gemm<false><<<grid, 512, GEMM_SMEM>>>(hhi, wqthi, nullptr, qhi, H_);
    }
    // Attention (TS=32, HMMA both phases)
    {
        dim3 grid(S_ / TS, B_);
        atten_kernel<<<grid, 256, ATT_SMEM>>>(hhi, qhi, out);
    }
}